// round 2
// baseline (speedup 1.0000x reference)
#include <cuda_runtime.h>
#include <math.h>

// Problem shapes (fixed by dataset): B=8192, S=6, H=1024
#define MAXB 8192
#define MAXH 1024

// Scratch (device globals: no allocations allowed in kernel_launch)
__device__ float g_cond[(size_t)MAXB * 2 * MAXH];   // [B, 2H]  (mean||max pools)
__device__ float g_Wf[(size_t)2 * MAXH * MAXH];     // W' = Wq @ Wk^T   [2H, H]
__device__ float g_cp[MAXH];                        // (bq+bp) @ Wk^T
__device__ float g_pp[MAXH];                        // Wp @ Wk^T
__device__ float g_r[(size_t)MAXB * MAXH];          // r = cond@W' + c' + gate*p'
__device__ float g_u[(size_t)MAXB * MAXH];          // u = sum_s w_s * ES[b,s,:]

// ---------------------------------------------------------------------------
// K0: pooling pass. One thread per (b,h): mean & max over S=6 rows.
// ---------------------------------------------------------------------------
__global__ void pool_kernel(const float* __restrict__ ES, float* __restrict__ cond,
                            int B, int S, int H) {
    int idx = blockIdx.x * blockDim.x + threadIdx.x;
    if (idx >= B * H) return;
    int b = idx / H, h = idx - b * H;
    const float* p = ES + (size_t)b * S * H + h;
    float v = p[0];
    float sum = v, mx = v;
    for (int s = 1; s < S; s++) {
        v = p[(size_t)s * H];
        sum += v;
        mx = fmaxf(mx, v);
    }
    float inv = 1.0f / (float)S;
    cond[(size_t)b * 2 * H + h] = sum * inv;
    cond[(size_t)b * 2 * H + H + h] = mx;
}

// ---------------------------------------------------------------------------
// K1b: c'[j] = sum_k (bq+bp)[k] * Wk[j,k];  p'[j] = sum_k Wp[k] * Wk[j,k]
// One warp per output j.
// ---------------------------------------------------------------------------
__global__ void fold_kernel(const float* __restrict__ Wk, const float* __restrict__ bq,
                            const float* __restrict__ bp, const float* __restrict__ Wp,
                            float* __restrict__ cp, float* __restrict__ pp, int H) {
    int gw = (blockIdx.x * blockDim.x + threadIdx.x) >> 5;
    int lane = threadIdx.x & 31;
    if (gw >= H) return;
    const float* row = Wk + (size_t)gw * H;
    float ac = 0.f, ap = 0.f;
    for (int k = lane * 4; k < H; k += 128) {
        float4 w  = *(const float4*)(row + k);
        float4 q  = *(const float4*)(bq + k);
        float4 p  = *(const float4*)(bp + k);
        float4 wp = *(const float4*)(Wp + k);
        ac += (q.x + p.x) * w.x + (q.y + p.y) * w.y + (q.z + p.z) * w.z + (q.w + p.w) * w.w;
        ap += wp.x * w.x + wp.y * w.y + wp.z * w.z + wp.w * w.w;
    }
    for (int o = 16; o; o >>= 1) {
        ac += __shfl_xor_sync(0xFFFFFFFFu, ac, o);
        ap += __shfl_xor_sync(0xFFFFFFFFu, ap, o);
    }
    if (lane == 0) { cp[gw] = ac; pp[gw] = ap; }
}

// ---------------------------------------------------------------------------
// Tiled fp32 SGEMM: C[M,N] = A[M,K] @ op(B)
//   BT=false: B is [K,N] row-major (NN)
//   BT=true : B is [N,K] row-major (NT, i.e. C = A @ B^T)
// EPI: 0 none | 1 C += e0[n] + gate[m]*e1[n] | 2 C += e0[n]
// 128x128 block tile, BK=16, 8x8 per thread, 256 threads.
// All of M,N multiples of 128 and K multiple of 16 (guaranteed by shapes).
// ---------------------------------------------------------------------------
template<bool BT, int EPI>
__global__ __launch_bounds__(256)
void sgemm_kernel(const float* __restrict__ A, const float* __restrict__ B,
                  float* __restrict__ C, int M, int N, int K,
                  const float* __restrict__ e0, const float* __restrict__ e1,
                  const float* __restrict__ gate) {
    constexpr int BM = 128, BN = 128, BK = 16, PAD = 4;
    __shared__ float As[BK][BM + PAD];
    __shared__ float Bs[BK][BN + PAD];
    const int tid = threadIdx.x;
    const int rowBase = blockIdx.y * BM;
    const int colBase = blockIdx.x * BN;
    const int tx = tid & 15, ty = tid >> 4;
    const int r4 = tid >> 2;          // 0..63
    const int c4 = (tid & 3) << 2;    // 0,4,8,12
    const int bR = tid >> 5;          // 0..7
    const int bC = (tid & 31) << 2;   // 0..124

    float acc[8][8] = {};

    for (int k0 = 0; k0 < K; k0 += BK) {
        // A tile (transposed into smem)
        #pragma unroll
        for (int p = 0; p < BM; p += 64) {
            float4 v = *(const float4*)(A + (size_t)(rowBase + r4 + p) * K + (k0 + c4));
            As[c4 + 0][r4 + p] = v.x;
            As[c4 + 1][r4 + p] = v.y;
            As[c4 + 2][r4 + p] = v.z;
            As[c4 + 3][r4 + p] = v.w;
        }
        // B tile
        if (BT) {
            #pragma unroll
            for (int p = 0; p < BN; p += 64) {
                float4 v = *(const float4*)(B + (size_t)(colBase + r4 + p) * K + (k0 + c4));
                Bs[c4 + 0][r4 + p] = v.x;
                Bs[c4 + 1][r4 + p] = v.y;
                Bs[c4 + 2][r4 + p] = v.z;
                Bs[c4 + 3][r4 + p] = v.w;
            }
        } else {
            #pragma unroll
            for (int p = 0; p < BK; p += 8) {
                float4 v = *(const float4*)(B + (size_t)(k0 + bR + p) * N + (colBase + bC));
                *(float4*)&Bs[bR + p][bC] = v;
            }
        }
        __syncthreads();

        #pragma unroll
        for (int kk = 0; kk < BK; kk++) {
            float a[8], bb[8];
            *(float4*)(a)      = *(const float4*)&As[kk][ty * 8];
            *(float4*)(a + 4)  = *(const float4*)&As[kk][ty * 8 + 4];
            *(float4*)(bb)     = *(const float4*)&Bs[kk][tx * 8];
            *(float4*)(bb + 4) = *(const float4*)&Bs[kk][tx * 8 + 4];
            #pragma unroll
            for (int i = 0; i < 8; i++)
                #pragma unroll
                for (int j = 0; j < 8; j++)
                    acc[i][j] = fmaf(a[i], bb[j], acc[i][j]);
        }
        __syncthreads();
    }

    #pragma unroll
    for (int i = 0; i < 8; i++) {
        int row = rowBase + ty * 8 + i;
        float g = (EPI == 1) ? gate[row] : 0.f;
        #pragma unroll
        for (int j = 0; j < 8; j += 4) {
            int col = colBase + tx * 8 + j;
            float4 v = { acc[i][j], acc[i][j + 1], acc[i][j + 2], acc[i][j + 3] };
            if (EPI == 1) {
                v.x += e0[col + 0] + g * e1[col + 0];
                v.y += e0[col + 1] + g * e1[col + 1];
                v.z += e0[col + 2] + g * e1[col + 2];
                v.w += e0[col + 3] + g * e1[col + 3];
            } else if (EPI == 2) {
                v.x += e0[col + 0];
                v.y += e0[col + 1];
                v.z += e0[col + 2];
                v.w += e0[col + 3];
            }
            *(float4*)(C + (size_t)row * N + col) = v;
        }
    }
}

// ---------------------------------------------------------------------------
// K3: per-batch scores -> softmax -> weights/entropy out, u = sum_s w_s ES[b,s,:]
// One block (256 threads) per batch row b. S=6, H=1024 hard requirements.
// ---------------------------------------------------------------------------
__global__ __launch_bounds__(256)
void attend_kernel(const float* __restrict__ ES, const float* __restrict__ r,
                   const float* __restrict__ sbias,
                   float* __restrict__ w_out, float* __restrict__ ent_out,
                   float* __restrict__ u_out) {
    const int b = blockIdx.x;
    const int tid = threadIdx.x;
    __shared__ float es_sh[6 * 1024];
    __shared__ float red[6][8];

    // Stage ES[b] (24 KB) into smem
    const float4* src = (const float4*)(ES + (size_t)b * 6 * 1024);
    float4* dst = (float4*)es_sh;
    #pragma unroll
    for (int i = 0; i < 6; i++) dst[tid + i * 256] = src[tid + i * 256];

    float4 rv = ((const float4*)(r + (size_t)b * 1024))[tid];
    __syncthreads();

    float4 ev[6];
    float sc[6];
    #pragma unroll
    for (int s = 0; s < 6; s++) {
        ev[s] = *(const float4*)&es_sh[s * 1024 + tid * 4];
        sc[s] = ev[s].x * rv.x + ev[s].y * rv.y + ev[s].z * rv.z + ev[s].w * rv.w;
    }
    #pragma unroll
    for (int s = 0; s < 6; s++)
        for (int o = 16; o; o >>= 1) sc[s] += __shfl_xor_sync(0xFFFFFFFFu, sc[s], o);
    if ((tid & 31) == 0) {
        #pragma unroll
        for (int s = 0; s < 6; s++) red[s][tid >> 5] = sc[s];
    }
    __syncthreads();

    // All threads redundantly finish the reduction + softmax (cheap, deterministic)
    float w[6], m = -1e30f;
    #pragma unroll
    for (int s = 0; s < 6; s++) {
        float t = sbias[s];
        #pragma unroll
        for (int wp = 0; wp < 8; wp++) t += red[s][wp];
        w[s] = t;
        m = fmaxf(m, t);
    }
    float Z = 0.f;
    #pragma unroll
    for (int s = 0; s < 6; s++) { w[s] = expf(w[s] - m); Z += w[s]; }
    float inv = 1.f / Z;
    float ent = 0.f;
    #pragma unroll
    for (int s = 0; s < 6; s++) {
        w[s] *= inv;
        ent -= w[s] * logf(w[s] + 1e-8f);
    }
    if (tid == 0) {
        #pragma unroll
        for (int s = 0; s < 6; s++) w_out[(size_t)b * 6 + s] = w[s];
        ent_out[b] = ent;
    }

    float4 u;
    u.x = w[0]*ev[0].x; u.y = w[0]*ev[0].y; u.z = w[0]*ev[0].z; u.w = w[0]*ev[0].w;
    #pragma unroll
    for (int s = 1; s < 6; s++) {
        u.x += w[s]*ev[s].x; u.y += w[s]*ev[s].y; u.z += w[s]*ev[s].z; u.w += w[s]*ev[s].w;
    }
    ((float4*)(u_out + (size_t)b * 1024))[tid] = u;
}

// ---------------------------------------------------------------------------
// Launch: pool -> fold -> W' = Wq@Wk^T -> r = cond@W' (+c' +gate*p')
//         -> attend (weights, entropy, u) -> fused = u@Wv + bv
// ---------------------------------------------------------------------------
extern "C" void kernel_launch(void* const* d_in, const int* in_sizes, int n_in,
                              void* d_out, int out_size) {
    const float* ES    = (const float*)d_in[0];
    // d_in[1] gene_context: unused by the reference
    const float* gate  = (const float*)d_in[2];
    const float* Wk    = (const float*)d_in[3];
    // d_in[4] bk: per-batch constant shift of all S scores -> cancels in softmax
    const float* Wv    = (const float*)d_in[5];
    const float* bv    = (const float*)d_in[6];
    const float* Wq    = (const float*)d_in[7];
    const float* bq    = (const float*)d_in[8];
    const float* Wp    = (const float*)d_in[9];
    const float* bp    = (const float*)d_in[10];
    const float* sbias = (const float*)d_in[11];

    const int B = in_sizes[2];    // pathogenicity_gate is [B,1]
    const int H = in_sizes[4];    // bk is [H]
    const int S = in_sizes[11];   // source_bias is [S]

    float* out       = (float*)d_out;
    float* out_fused = out;                         // [B,H]
    float* out_w     = out + (size_t)B * H;         // [B,S]
    float* out_ent   = out_w + (size_t)B * S;       // [B,1]

    float *cond, *Wf, *cp, *pp, *rr, *uu;
    cudaGetSymbolAddress((void**)&cond, g_cond);
    cudaGetSymbolAddress((void**)&Wf,   g_Wf);
    cudaGetSymbolAddress((void**)&cp,   g_cp);
    cudaGetSymbolAddress((void**)&pp,   g_pp);
    cudaGetSymbolAddress((void**)&rr,   g_r);
    cudaGetSymbolAddress((void**)&uu,   g_u);

    // K0: pools
    pool_kernel<<<(B * H + 255) / 256, 256>>>(ES, cond, B, S, H);
    // K1b: bias folds through Wk^T
    fold_kernel<<<(H * 32 + 255) / 256, 256>>>(Wk, bq, bp, Wp, cp, pp, H);
    // K1: W' = Wq @ Wk^T   [2H, H]
    {
        dim3 grid(H / 128, (2 * H) / 128);
        sgemm_kernel<true, 0><<<grid, 256>>>(Wq, Wk, Wf, 2 * H, H, H,
                                             nullptr, nullptr, nullptr);
    }
    // K2: r = cond @ W' + c' + gate * p'   [B, H]
    {
        dim3 grid(H / 128, B / 128);
        sgemm_kernel<false, 1><<<grid, 256>>>(cond, Wf, rr, B, H, 2 * H,
                                              cp, pp, gate);
    }
    // K3: scores/softmax/entropy/u
    attend_kernel<<<B, 256>>>(ES, rr, sbias, out_w, out_ent, uu);
    // K4: fused = u @ Wv + bv   [B, H]
    {
        dim3 grid(H / 128, B / 128);
        sgemm_kernel<false, 2><<<grid, 256>>>(uu, Wv, out_fused, B, H, H,
                                              bv, nullptr, nullptr);
    }
}